// round 2
// baseline (speedup 1.0000x reference)
#include <cuda_runtime.h>

// BayesianFlowNetworkDiscretised: per-element tiny MLP + discretised-bin CDF output.
// out[b,d,k] = cdf_upper - cdf_lower with telescoping boundaries.

constexpr int K = 16;
constexpr int H = 16;

__device__ __forceinline__ float tanh_approx(float x) {
    float y;
    asm("tanh.approx.f32 %0, %1;" : "=f"(y) : "f"(x));
    return y;
}

__global__ __launch_bounds__(256) void bfn_kernel(
    const float* __restrict__ mu,
    const float* __restrict__ t,
    const float* __restrict__ W1,
    const float* __restrict__ b1,
    const float* __restrict__ W2,
    const float* __restrict__ b2,
    float* __restrict__ out,
    int Dn)
{
    __shared__ float s_w1[H];   // W1[0][j]
    __shared__ float s_c[H];    // t*W1[1][j] + b1[j]  (row-folded)
    __shared__ float s_w2a[H];  // W2[j][0]
    __shared__ float s_w2b[H];  // W2[j][1]
    __shared__ float s_scal[5]; // inv_gamma, var_scale, tmin_flag, b2[0], b2[1]

    const int b = blockIdx.y;

    if (threadIdx.x < H) {
        const int j = threadIdx.x;
        const float tv = t[b];
        s_w1[j]  = W1[j];
        s_c[j]   = fmaf(tv, W1[H + j], b1[j]);
        s_w2a[j] = W2[2 * j];
        s_w2b[j] = W2[2 * j + 1];
        if (j == 0) {
            // gamma = 1 - 0.02^(2t) = 1 - 2^(2t * log2(0.02))
            const float g = 1.0f - exp2f(2.0f * tv * -5.6438561897747395f);
            s_scal[0] = 1.0f / g;
            s_scal[1] = sqrtf((1.0f - g) / g);
            s_scal[2] = (tv < 1e-6f) ? 1.0f : 0.0f;
            s_scal[3] = b2[0];
            s_scal[4] = b2[1];
        }
    }
    __syncthreads();

    const int d = blockIdx.x * 256 + threadIdx.x;
    if (d >= Dn) return;

    const size_t elem = (size_t)b * Dn + d;
    const float m = mu[elem];

    // tiny MLP: h_j = gelu_tanh(m*W1[0][j] + c_j); out = h @ W2 + b2
    float acc0 = s_scal[3];
    float acc1 = s_scal[4];
#pragma unroll
    for (int j = 0; j < H; j++) {
        const float a  = fmaf(m, s_w1[j], s_c[j]);
        const float a2 = a * a;
        // sqrt(2/pi)=0.7978845608; 0.7978845608*0.044715=0.0356774081
        const float inner = a * fmaf(0.0356774081f, a2, 0.7978845608f);
        const float th = tanh_approx(inner);
        const float hv = 0.5f * a * (1.0f + th);
        acc0 = fmaf(hv, s_w2a[j], acc0);
        acc1 = fmaf(hv, s_w2b[j], acc1);
    }

    const float inv_gamma = s_scal[0];
    const float vs        = s_scal[1];
    const bool  tmin      = s_scal[2] > 0.5f;

    float mu_x = fmaf(m, inv_gamma, -vs * acc0);
    float ln   = fminf(fmaxf(acc1, -10.0f), 10.0f);
    float sg   = fmaxf(vs * __expf(ln), 0.02f);
    if (tmin) { mu_x = 0.0f; sg = 1.0f; }

    // inv = 1/(sigma*sqrt(2))
    const float inv = __fdividef(0.70710678118654752f, sg);

    // boundaries b_j = -1 + j/8, j=1..15; edges are exactly -1 / +1 in erf space
    float r[K];
    float eprev = -1.0f;
#pragma unroll
    for (int j = 1; j < K; j++) {
        const float bj = -1.0f + 0.125f * (float)j;
        const float e = erff((bj - mu_x) * inv);
        r[j - 1] = 0.5f * (e - eprev);
        eprev = e;
    }
    r[K - 1] = 0.5f * (1.0f - eprev);

    float4* o = reinterpret_cast<float4*>(out + elem * K);
    o[0] = make_float4(r[0],  r[1],  r[2],  r[3]);
    o[1] = make_float4(r[4],  r[5],  r[6],  r[7]);
    o[2] = make_float4(r[8],  r[9],  r[10], r[11]);
    o[3] = make_float4(r[12], r[13], r[14], r[15]);
}

extern "C" void kernel_launch(void* const* d_in, const int* in_sizes, int n_in,
                              void* d_out, int out_size) {
    const float* mu = (const float*)d_in[0];
    const float* t  = (const float*)d_in[1];
    const float* W1 = (const float*)d_in[2];
    const float* b1 = (const float*)d_in[3];
    const float* W2 = (const float*)d_in[4];
    const float* b2 = (const float*)d_in[5];
    float* out = (float*)d_out;

    const int B = in_sizes[1];           // t has B elements
    const int D = in_sizes[0] / B;       // mu is [B, D]

    dim3 grid((D + 255) / 256, B);
    bfn_kernel<<<grid, 256>>>(mu, t, W1, b1, W2, b2, out, D);
}

// round 3
// speedup vs baseline: 1.2357x; 1.2357x over previous
#include <cuda_runtime.h>

// BayesianFlowNetworkDiscretised: per-element tiny MLP + discretised-bin CDF.
// R2: replace erff (≈28 instrs) with tanh-based erf (7 instrs):
//     erf(x) ~= tanh(x * (C0 + C1 s + C2 s^2 + C3 s^3)), s = min(x^2, SCAP)
// fit max abs error ~7e-5; saturation exact via s-clamp (u ~ 2.22*x beyond cap).

constexpr int K = 16;
constexpr int H = 16;

__device__ __forceinline__ float tanh_approx(float x) {
    float y;
    asm("tanh.approx.f32 %0, %1;" : "=f"(y) : "f"(x));
    return y;
}

// erf(x) ~= tanh(x * g(x^2)) coefficients (collocated at s=0,1,4,9)
#define ERF_C0 1.1283792f
#define ERF_C1 0.1038252f
#define ERF_C2 (-0.00176024f)
#define ERF_C3 (-2.46588e-5f)
#define ERF_SCAP 15.3664f

__global__ __launch_bounds__(256) void bfn_kernel(
    const float* __restrict__ mu,
    const float* __restrict__ t,
    const float* __restrict__ W1,
    const float* __restrict__ b1,
    const float* __restrict__ W2,
    const float* __restrict__ b2,
    float* __restrict__ out,
    int Dn)
{
    __shared__ float s_w1[H];    // W1[0][j]
    __shared__ float s_c[H];     // t*W1[1][j] + b1[j]
    __shared__ float s_w2a[H];   // 0.5 * W2[j][0]
    __shared__ float s_w2b[H];   // 0.5 * W2[j][1]
    __shared__ float s_scal[8];  // inv_gamma, vs, tmin, a0, b0, a1, b1

    const int b = blockIdx.y;

    if (threadIdx.x < H) {
        const int j = threadIdx.x;
        const float tv = t[b];
        s_w1[j]  = W1[j];
        s_c[j]   = fmaf(tv, W1[H + j], b1[j]);
        s_w2a[j] = 0.5f * W2[2 * j];
        s_w2b[j] = 0.5f * W2[2 * j + 1];
        if (j == 0) {
            // gamma = 1 - 0.02^(2t) = 1 - 2^(2t*log2(0.02))
            const float g = 1.0f - exp2f(2.0f * tv * -5.6438561897747395f);
            s_scal[0] = 1.0f / g;
            s_scal[1] = sqrtf((1.0f - g) / g);
            s_scal[2] = (tv < 1e-6f) ? 1.0f : 0.0f;
        }
    }
    __syncthreads();
    if (threadIdx.x == 0) {
        // fold linear-gelu half into row constants:
        // acc0 = alpha0 + beta0*m + sum_j a_j*th_j*(0.5 w2a_j)
        float a0 = b2[0], a1v = b2[1], be0 = 0.0f, be1 = 0.0f;
#pragma unroll
        for (int j = 0; j < H; j++) {
            a0  = fmaf(s_c[j],  s_w2a[j], a0);
            a1v = fmaf(s_c[j],  s_w2b[j], a1v);
            be0 = fmaf(s_w1[j], s_w2a[j], be0);
            be1 = fmaf(s_w1[j], s_w2b[j], be1);
        }
        s_scal[3] = a0;  s_scal[4] = be0;
        s_scal[5] = a1v; s_scal[6] = be1;
    }
    __syncthreads();

    const int d = blockIdx.x * 256 + threadIdx.x;
    if (d >= Dn) return;

    const size_t elem = (size_t)b * Dn + d;
    const float m = mu[elem];

    // tiny MLP (tanh-gelu, identical formula to jax.nn.gelu approximate)
    float acc0 = fmaf(m, s_scal[4], s_scal[3]);
    float acc1 = fmaf(m, s_scal[6], s_scal[5]);
#pragma unroll
    for (int j = 0; j < H; j++) {
        const float a   = fmaf(m, s_w1[j], s_c[j]);
        const float a2  = a * a;
        // sqrt(2/pi)=0.7978845608; *0.044715 = 0.0356774081
        const float inner = a * fmaf(0.0356774081f, a2, 0.7978845608f);
        const float ath = a * tanh_approx(inner);
        acc0 = fmaf(ath, s_w2a[j], acc0);
        acc1 = fmaf(ath, s_w2b[j], acc1);
    }

    const float inv_gamma = s_scal[0];
    const float vs        = s_scal[1];
    const bool  tmin      = s_scal[2] > 0.5f;

    float mu_x = fmaf(m, inv_gamma, -vs * acc0);
    float ln   = fminf(fmaxf(acc1, -10.0f), 10.0f);
    float sg   = fmaxf(vs * __expf(ln), 0.02f);
    if (tmin) { mu_x = 0.0f; sg = 1.0f; }

    const float inv  = __fdividef(0.70710678118654752f, sg);  // 1/(sigma*sqrt(2))
    const float z1   = (-0.875f - mu_x) * inv;                 // boundary j=1
    const float step = 0.125f * inv;

    // 15 interior boundary erfs via tanh approximation
    float e[K - 1];
#pragma unroll
    for (int j = 0; j < K - 1; j++) {
        const float z = fmaf(step, (float)j, z1);
        float s = z * z;
        s = fminf(s, ERF_SCAP);
        const float p = fmaf(fmaf(fmaf(ERF_C3, s, ERF_C2), s, ERF_C1), s, ERF_C0);
        e[j] = tanh_approx(z * p);
    }

    float h[K - 1];
#pragma unroll
    for (int j = 0; j < K - 1; j++) h[j] = 0.5f * e[j];

    float r[K];
    r[0] = h[0] + 0.5f;
#pragma unroll
    for (int j = 1; j < K - 1; j++) r[j] = h[j] - h[j - 1];
    r[K - 1] = 0.5f - h[K - 2];

    float4* o = reinterpret_cast<float4*>(out + elem * K);
    o[0] = make_float4(r[0],  r[1],  r[2],  r[3]);
    o[1] = make_float4(r[4],  r[5],  r[6],  r[7]);
    o[2] = make_float4(r[8],  r[9],  r[10], r[11]);
    o[3] = make_float4(r[12], r[13], r[14], r[15]);
}

extern "C" void kernel_launch(void* const* d_in, const int* in_sizes, int n_in,
                              void* d_out, int out_size) {
    const float* mu = (const float*)d_in[0];
    const float* t  = (const float*)d_in[1];
    const float* W1 = (const float*)d_in[2];
    const float* b1 = (const float*)d_in[3];
    const float* W2 = (const float*)d_in[4];
    const float* b2 = (const float*)d_in[5];
    float* out = (float*)d_out;

    const int B = in_sizes[1];           // t has B elements
    const int D = in_sizes[0] / B;       // mu is [B, D]

    dim3 grid((D + 255) / 256, B);
    bfn_kernel<<<grid, 256>>>(mu, t, W1, b1, W2, b2, out, D);
}